// round 15
// baseline (speedup 1.0000x reference)
#include <cuda_runtime.h>
#include <math.h>

// ---------------- constants matching the reference ----------------
#define HH 121
#define WW 121
#define NE 225
#define NB 8
#define N_INTERP 200
#define RET_PER_DVA 280.0f
#define XRANGE0 (-15.0f)
#define YRANGE0 (-15.0f)
#define XYSTEP 0.25f
#define XLOWc (-4200.0f)
#define YLOWc (-4200.0f)
#define STEP_Xc (8400.0f/199.0f)
#define STEP_Yc (8400.0f/199.0f)
#define OD_OFF_Xc (15.5f*280.0f)
#define AMP_CUTOFF 0.25f
#define PIc 3.14159265358979323846f
#define TEMP1c (4.0f*PIc)
#define NEG_HALF_LOG2E (-0.7213475204444817f)   // -0.5*log2(e)
#define LOG2_045 (-1.1520030934450498f)         // log2(0.45)
#define CULL_T 22.0f                   // exp2(-22) ~ 2.4e-7 per dropped term

#define NPIX (HH*WW)
#define TILES_X 8
#define TILES_Y 8
#define NBLK_PER_B (TILES_X * TILES_Y)   // 64

// per-(b,e) table:  e*2+0: (cx, cy2, R2cull, bright)   e*2+1: (c00, c01, c11, 2*c11)
__device__ float4 g_tab[NB][NE * 2];
__device__ int    g_flag[NB];          // 0 -> table not ready (self-resetting)
__device__ int    g_cnt[NB];           // consumer count      (self-resetting)

__device__ __forceinline__ float ex2_fast(float x) {
    float r;
    asm("ex2.approx.ftz.f32 %0, %1;" : "=f"(r) : "f"(x));
    return r;
}

// ONE kernel. grid (8, 8, NB) = 512 blocks (single wave: <=8 blocks/SM by
// warp slots, only 3.46 needed -> all co-resident, spin is deadlock-free).
//
// Producer: block (0,0,b) computes the full 225-electrode table for batch b
//   (one electrode per thread), release-publishes via fence+atomic flag.
// All blocks: acquire-spin on flag, then load table (__ldcg), per-lane cull
//   vs own 16x16 tile, block-wide deterministic compaction of survivors,
//   balanced survivor loop (warp w takes s = w, w+8, ...; 8-row finite
//   differences), block-local 8-warp reduction in fixed order -> STG.
// Flag/counter reset by the 64th consumer of each batch (graph-replay safe).
__global__ __launch_bounds__(256) void mvg_kernel(
        const float* __restrict__ stim,
        const float* __restrict__ params,
        const float* __restrict__ elec_x,
        const float* __restrict__ elec_y,
        const float* __restrict__ slopes,
        float* __restrict__ out) {
    __shared__ float4 cA[NE];          // compacted survivors: cx, cy2, -, bright
    __shared__ float4 cB[NE];          // c00, c01, c11, 2*c11
    __shared__ float  spart[8][256];   // [warp][pixel-in-tile]
    __shared__ int    wcnt[8];
    __shared__ int    s_len;

    int b = blockIdx.z;
    int tid = threadIdx.x;
    int lane = tid & 31, w = tid >> 5;

    // ---------------- producer: build the per-batch table ----------------
    if (blockIdx.x == 0 && blockIdx.y == 0) {
        if (tid < NE) {
            int e = tid;
            const float* P = params + b * 13;
            float rho = P[0], lam = P[1], osc = P[2];
            float a0 = P[3], a1 = P[4], a2 = P[5], a3 = P[6], a4 = P[7];
            float impx = P[8], impy = P[9], rot = P[10], lodx = P[11];
            float cr = __cosf(rot), sr = __sinf(rot);

            float exv = elec_x[e] * cr - elec_y[e] * sr + impx;
            float eyv = elec_x[e] * sr + elec_y[e] * cr + impy;
            float freq = stim[(b * NE + e) * 3 + 0];
            float amp  = stim[(b * NE + e) * 3 + 1];
            float pdur = stim[(b * NE + e) * 3 + 2];

            float cx = 0.f, cy2 = 0.f, R2c = -1.0f, bright = 0.f;
            float c00 = 0.f, c01 = 0.f, c11 = 0.f;

            if (amp > AMP_CUTOFF) {
                float offx = lodx - OD_OFF_Xc;
                float qx = (exv - offx - XLOWc) * (1.0f / STEP_Xc);
                float qy = (eyv - YLOWc) * (1.0f / STEP_Yc);

                float fx = fminf(fmaxf(floorf(qx), 0.f), (float)(N_INTERP - 2));
                float fy = fminf(fmaxf(floorf(qy), 0.f), (float)(N_INTERP - 2));
                int ix = (int)fx, iy = (int)fy;
                float ax = fminf(fmaxf(qx - fx, 0.f), 1.f);
                float ay = fminf(fmaxf(qy - fy, 0.f), 1.f);
                float g00 = slopes[iy * N_INTERP + ix];
                float g01 = slopes[iy * N_INTERP + ix + 1];
                float g10 = slopes[(iy + 1) * N_INTERP + ix];
                float g11 = slopes[(iy + 1) * N_INTERP + ix + 1];
                float top = g00 + ax * (g01 - g00);
                float bot = g10 + ax * (g11 - g10);
                float th = top + ay * (bot - top);
                if (th < -PIc * 0.5f) th += PIc;
                th *= osc;

                float rs = fmaxf(rho * amp * a3, 1.0f);
                // 0.45^-a4 * pdur^a4 = exp2(a4*(log2(pdur) - log2(0.45)))
                float ls = lam * ex2_fast(a4 * (__log2f(pdur) - LOG2_045));
                ls = fminf(fmaxf(ls, 0.f), 0.99f);
                bright = a0 * ex2_fast(a1 * __log2f(fmaxf(amp, 1e-5f))) + a2 * freq;

                float t2 = sqrtf(1.0f - ls * ls);
                float sy = __fdividef(rs, TEMP1c * t2);
                float sx = rs * t2 * (1.0f / TEMP1c);
                float s = __sinf(th), c = __cosf(th);
                float cov00 = sx * c * c + sy * s * s;
                float cov01 = (sx - sy) * s * c;
                float cov11 = sx * s * s + sy * c * c;
                float det = cov00 * cov11 - cov01 * cov01;
                float rdet = __fdividef(1.0f, det);
                float inv00 = cov11 * rdet;
                float inv01 = -cov01 * rdet;
                float inv11 = cov00 * rdet;

                c00 = NEG_HALF_LOG2E * inv00;
                c01 = 2.0f * NEG_HALF_LOG2E * inv01;
                c11 = NEG_HALF_LOG2E * inv11;

                cx = (exv / RET_PER_DVA - XRANGE0) / XYSTEP;
                float cy = (float)HH - (eyv / RET_PER_DVA - YRANGE0) / XYSTEP;
                cy2 = 120.0f - cy;   // d1 = cy2 - r

                // cull radius^2: |t| >= lmin*dist^2; skip when lmin*dist^2 > CULL_T
                float trn = -(c00 + c11);
                float dQ  = c00 * c11 - 0.25f * c01 * c01;
                float disc = fmaxf(trn * trn - 4.0f * dQ, 0.f);
                float lmin = 0.5f * (trn - sqrtf(disc));
                R2c = __fdividef(CULL_T, fmaxf(lmin, 1e-20f));
            }

            g_tab[b][e * 2 + 0] = make_float4(cx, cy2, R2c, bright);
            g_tab[b][e * 2 + 1] = make_float4(c00, c01, c11, 2.0f * c11);
        }
        __threadfence();               // publish table (each writer fences)
        __syncthreads();
        if (tid == 0) atomicExch(&g_flag[b], 1);
    }

    // ---------------- acquire: wait for this batch's table ---------------
    if (tid == 0) {
        while (atomicAdd(&g_flag[b], 0) == 0) __nanosleep(64);
    }
    __syncthreads();

    // tile center (block-uniform)
    float wcx = (float)(blockIdx.x * 16) + 7.5f;
    float wcy = (float)(blockIdx.y * 16) + 7.5f;

    // ---------------- phase 1: load + cull + block compaction ------------
    bool surv = false;
    float4 A, Bv;
    if (tid < NE) {
        A  = __ldcg(&g_tab[b][tid * 2 + 0]);
        Bv = __ldcg(&g_tab[b][tid * 2 + 1]);
        float dx = fmaxf(fabsf(wcx - A.x) - 7.5f, 0.f);
        float dy = fmaxf(fabsf(wcy - A.y) - 7.5f, 0.f);
        surv = (fmaf(dx, dx, dy * dy) <= A.z);   // R2c=-1 for inactive
    }
    unsigned mask = __ballot_sync(0xffffffffu, surv);
    if (lane == 0) wcnt[w] = __popc(mask);
    __syncthreads();
    int off = 0;
#pragma unroll
    for (int i = 0; i < 8; i++) off += (i < w) ? wcnt[i] : 0;
    if (tid == 0) {
        int tot = 0;
#pragma unroll
        for (int i = 0; i < 8; i++) tot += wcnt[i];
        s_len = tot;
        // retire: 64th consumer of this batch resets flag+counter for replay
        int old = atomicAdd(&g_cnt[b], 1);
        if (old == NBLK_PER_B - 1) {
            atomicExch(&g_cnt[b], 0);
            atomicExch(&g_flag[b], 0);
        }
    }
    if (surv) {
        int slot = off + __popc(mask & ((1u << lane) - 1u));
        cA[slot] = A;
        cB[slot] = Bv;
    }
    __syncthreads();
    int n = s_len;

    // ---------------- phase 2: balanced survivor loop (16x16, 8-row FD) --
    int lx = lane & 15;
    int ly = lane >> 4;
    float cf  = (float)(blockIdx.x * 16 + lx);
    float rf0 = (float)(blockIdx.y * 16 + ly * 8);

    float acc[8];
#pragma unroll
    for (int i = 0; i < 8; i++) acc[i] = 0.f;

    for (int s = w; s < n; s += 8) {
        float4 SA = cA[s];             // cx, cy2, -, bright
        float4 SB = cB[s];             // c00, c01, c11, 2*c11

        float d0 = cf - SA.x;
        float k1 = SB.y * d0;          // c01*d0
        float k0 = (SB.x * d0) * d0;   // c00*d0^2
        float d1 = SA.y - rf0;

        float t   = fmaf(fmaf(SB.z, d1, k1), d1, k0);
        float dlt = fmaf(SB.z, fmaf(-2.0f, d1, 1.0f), -k1);

#pragma unroll
        for (int i = 0; i < 8; i++) {
            acc[i] = fmaf(SA.w, ex2_fast(t), acc[i]);
            t += dlt;
            dlt += SB.w;               // 2*c11
        }
    }

    // partials: pixel index in tile = (ly*8 + i)*16 + lx
    int pbase = ly * 128 + lx;
#pragma unroll
    for (int i = 0; i < 8; i++)
        spart[w][pbase + i * 16] = acc[i];
    __syncthreads();

    // ---------------- phase 3: block-local reduction ---------------------
    {
        // fixed warp order -> deterministic fp sum
        float v = spart[0][tid] + spart[1][tid] + spart[2][tid] + spart[3][tid]
                + spart[4][tid] + spart[5][tid] + spart[6][tid] + spart[7][tid];
        int r  = blockIdx.y * 16 + (tid >> 4);
        int cc = blockIdx.x * 16 + (tid & 15);
        if (r < HH && cc < WW)
            out[b * NPIX + r * WW + cc] = v;
    }
}

extern "C" void kernel_launch(void* const* d_in, const int* in_sizes, int n_in,
                              void* d_out, int out_size) {
    const float* stim   = (const float*)d_in[0];  // (8,225,3)
    const float* params = (const float*)d_in[1];  // (8,13)
    const float* ex     = (const float*)d_in[2];  // (1,225)
    const float* ey     = (const float*)d_in[3];  // (1,225)
    const float* slopes = (const float*)d_in[4];  // (200,200)
    // d_in[5] = pixelgrid: implied analytically, unused

    dim3 grid(TILES_X, TILES_Y, NB);   // (8,8,8) = 512 blocks x 256 threads
    mvg_kernel<<<grid, 256>>>(stim, params, ex, ey, slopes, (float*)d_out);
}

// round 16
// speedup vs baseline: 1.1697x; 1.1697x over previous
#include <cuda_runtime.h>
#include <math.h>

// ---------------- constants matching the reference ----------------
#define HH 121
#define WW 121
#define NE 225
#define NB 8
#define N_INTERP 200
#define RET_PER_DVA 280.0f
#define XRANGE0 (-15.0f)
#define YRANGE0 (-15.0f)
#define XYSTEP 0.25f
#define XLOWc (-4200.0f)
#define YLOWc (-4200.0f)
#define STEP_Xc (8400.0f/199.0f)
#define STEP_Yc (8400.0f/199.0f)
#define OD_OFF_Xc (15.5f*280.0f)
#define AMP_CUTOFF 0.25f
#define PIc 3.14159265358979323846f
#define TEMP1c (4.0f*PIc)
#define NEG_HALF_LOG2E (-0.7213475204444817f)   // -0.5*log2(e)
#define HALF_LOG2E 0.7213475204444817f
#define LOG2_045 (-1.1520030934450498f)         // log2(0.45)
#define CULL_T 22.0f                   // exp2(-22) ~ 2.4e-7 per dropped term

#define NPIX (HH*WW)
#define TILES_X 8
#define TILES_Y 8

__device__ __forceinline__ float ex2_fast(float x) {
    float r;
    asm("ex2.approx.ftz.f32 %0, %1;" : "=f"(r) : "f"(x));
    return r;
}

// ONE kernel. grid (8, 8, NB) = 512 blocks, block 256 (8 warps), 16x16 tile.
// Phase 1a (cheap cull, all 225 electrodes, one per thread):
//   center (cx,cy2) needs only the rotation/affine path; the cull radius
//   needs only sy: cov eigenvalues are exactly (sx, sy) with sy >= sx, so
//   lmin(-Q) = 0.7213/sy  ->  R2c = CULL_T * sy / 0.7213.  ~30 instrs,
//   3 MUFU, no slopes load, no covariance.
// Compaction: block-wide deterministic (ordered by e) survivor INDEX list.
// Phase 1b: only survivors (thread i -> survivor i) run the full chain
//   (slopes interp, theta, covariance inverse) and fill cA/cB.
// Phase 2: balanced survivor loop (warp w takes s = w, w+8, ...), 16x16
//   tile per warp, 8-row finite differences.
// Phase 3: block-local 8-warp reduction in fixed order -> STG.
__global__ __launch_bounds__(256) void mvg_kernel(
        const float* __restrict__ stim,
        const float* __restrict__ params,
        const float* __restrict__ elec_x,
        const float* __restrict__ elec_y,
        const float* __restrict__ slopes,
        float* __restrict__ out) {
    __shared__ int    cIdx[NE];        // survivor electrode ids (ascending)
    __shared__ float4 cA[NE];          // survivors: cx, cy2, -, bright
    __shared__ float4 cB[NE];          // c00, c01, c11, 2*c11
    __shared__ float  spart[8][256];   // [warp][pixel-in-tile]
    __shared__ int    wcnt[8];
    __shared__ int    s_len;

    int b = blockIdx.z;
    int tid = threadIdx.x;
    int lane = tid & 31, w = tid >> 5;

    // tile center (block-uniform)
    float wcx = (float)(blockIdx.x * 16) + 7.5f;
    float wcy = (float)(blockIdx.y * 16) + 7.5f;

    const float* P = params + b * 13;

    // ---------------- phase 1a: cheap cull over all electrodes -----------
    bool surv = false;
    if (tid < NE) {
        float rho = P[0], lam = P[1];
        float a3 = P[6], a4 = P[7];
        float impx = P[8], impy = P[9], rot = P[10];
        float cr = __cosf(rot), sr = __sinf(rot);

        float exv = elec_x[tid] * cr - elec_y[tid] * sr + impx;
        float eyv = elec_x[tid] * sr + elec_y[tid] * cr + impy;
        float amp  = stim[(b * NE + tid) * 3 + 1];
        float pdur = stim[(b * NE + tid) * 3 + 2];

        if (amp > AMP_CUTOFF) {
            float cx = (exv / RET_PER_DVA - XRANGE0) / XYSTEP;
            float cy = (float)HH - (eyv / RET_PER_DVA - YRANGE0) / XYSTEP;
            float cy2 = 120.0f - cy;

            float rs = fmaxf(rho * amp * a3, 1.0f);
            float ls = lam * ex2_fast(a4 * (__log2f(pdur) - LOG2_045));
            ls = fminf(fmaxf(ls, 0.f), 0.99f);
            float t2 = sqrtf(1.0f - ls * ls);
            float sy = __fdividef(rs, TEMP1c * t2);       // max eigenvalue of cov
            float R2c = (CULL_T / HALF_LOG2E) * sy;       // CULL_T / lmin, exact

            float dx = fmaxf(fabsf(wcx - cx) - 7.5f, 0.f);
            float dy = fmaxf(fabsf(wcy - cy2) - 7.5f, 0.f);
            surv = (fmaf(dx, dx, dy * dy) <= R2c);
        }
    }

    // block-wide deterministic compaction (ascending e)
    unsigned mask = __ballot_sync(0xffffffffu, surv);
    if (lane == 0) wcnt[w] = __popc(mask);
    __syncthreads();
    int off = 0;
#pragma unroll
    for (int i = 0; i < 8; i++) off += (i < w) ? wcnt[i] : 0;
    if (tid == 0) {
        int tot = 0;
#pragma unroll
        for (int i = 0; i < 8; i++) tot += wcnt[i];
        s_len = tot;
    }
    if (surv) {
        int slot = off + __popc(mask & ((1u << lane) - 1u));
        cIdx[slot] = tid;
    }
    __syncthreads();
    int n = s_len;

    // ---------------- phase 1b: full chain for survivors only ------------
    if (tid < n) {
        int e = cIdx[tid];
        float rho = P[0], lam = P[1], osc = P[2];
        float a0 = P[3], a1 = P[4], a2 = P[5], a3 = P[6], a4 = P[7];
        float impx = P[8], impy = P[9], rot = P[10], lodx = P[11];
        float cr = __cosf(rot), sr = __sinf(rot);

        float exv = elec_x[e] * cr - elec_y[e] * sr + impx;
        float eyv = elec_x[e] * sr + elec_y[e] * cr + impy;
        float freq = stim[(b * NE + e) * 3 + 0];
        float amp  = stim[(b * NE + e) * 3 + 1];
        float pdur = stim[(b * NE + e) * 3 + 2];

        float offx = lodx - OD_OFF_Xc;
        float qx = (exv - offx - XLOWc) * (1.0f / STEP_Xc);
        float qy = (eyv - YLOWc) * (1.0f / STEP_Yc);

        float fx = fminf(fmaxf(floorf(qx), 0.f), (float)(N_INTERP - 2));
        float fy = fminf(fmaxf(floorf(qy), 0.f), (float)(N_INTERP - 2));
        int ix = (int)fx, iy = (int)fy;
        float ax = fminf(fmaxf(qx - fx, 0.f), 1.f);
        float ay = fminf(fmaxf(qy - fy, 0.f), 1.f);
        float g00 = slopes[iy * N_INTERP + ix];
        float g01 = slopes[iy * N_INTERP + ix + 1];
        float g10 = slopes[(iy + 1) * N_INTERP + ix];
        float g11 = slopes[(iy + 1) * N_INTERP + ix + 1];
        float top = g00 + ax * (g01 - g00);
        float bot = g10 + ax * (g11 - g10);
        float th = top + ay * (bot - top);
        if (th < -PIc * 0.5f) th += PIc;
        th *= osc;

        float rs = fmaxf(rho * amp * a3, 1.0f);
        float ls = lam * ex2_fast(a4 * (__log2f(pdur) - LOG2_045));
        ls = fminf(fmaxf(ls, 0.f), 0.99f);
        float bright = a0 * ex2_fast(a1 * __log2f(fmaxf(amp, 1e-5f))) + a2 * freq;

        float t2 = sqrtf(1.0f - ls * ls);
        float sy = __fdividef(rs, TEMP1c * t2);
        float sx = rs * t2 * (1.0f / TEMP1c);
        float s = __sinf(th), c = __cosf(th);
        float cov00 = sx * c * c + sy * s * s;
        float cov01 = (sx - sy) * s * c;
        float cov11 = sx * s * s + sy * c * c;
        float det = cov00 * cov11 - cov01 * cov01;
        float rdet = __fdividef(1.0f, det);
        float inv00 = cov11 * rdet;
        float inv01 = -cov01 * rdet;
        float inv11 = cov00 * rdet;

        float c00 = NEG_HALF_LOG2E * inv00;
        float c01 = 2.0f * NEG_HALF_LOG2E * inv01;
        float c11 = NEG_HALF_LOG2E * inv11;

        float cx = (exv / RET_PER_DVA - XRANGE0) / XYSTEP;
        float cy = (float)HH - (eyv / RET_PER_DVA - YRANGE0) / XYSTEP;
        float cy2 = 120.0f - cy;   // d1 = cy2 - r

        cA[tid] = make_float4(cx, cy2, 0.f, bright);
        cB[tid] = make_float4(c00, c01, c11, 2.0f * c11);
    }
    __syncthreads();

    // ---------------- phase 2: balanced survivor loop (16x16, 8-row FD) --
    int lx = lane & 15;
    int ly = lane >> 4;
    float cf  = (float)(blockIdx.x * 16 + lx);
    float rf0 = (float)(blockIdx.y * 16 + ly * 8);

    float acc[8];
#pragma unroll
    for (int i = 0; i < 8; i++) acc[i] = 0.f;

    for (int s = w; s < n; s += 8) {
        float4 SA = cA[s];             // cx, cy2, -, bright
        float4 SB = cB[s];             // c00, c01, c11, 2*c11

        float d0 = cf - SA.x;
        float k1 = SB.y * d0;          // c01*d0
        float k0 = (SB.x * d0) * d0;   // c00*d0^2
        float d1 = SA.y - rf0;

        float t   = fmaf(fmaf(SB.z, d1, k1), d1, k0);
        float dlt = fmaf(SB.z, fmaf(-2.0f, d1, 1.0f), -k1);

#pragma unroll
        for (int i = 0; i < 8; i++) {
            acc[i] = fmaf(SA.w, ex2_fast(t), acc[i]);
            t += dlt;
            dlt += SB.w;               // 2*c11
        }
    }

    // partials: pixel index in tile = (ly*8 + i)*16 + lx
    int pbase = ly * 128 + lx;
#pragma unroll
    for (int i = 0; i < 8; i++)
        spart[w][pbase + i * 16] = acc[i];
    __syncthreads();

    // ---------------- phase 3: block-local reduction ---------------------
    {
        // fixed warp order -> deterministic fp sum
        float v = spart[0][tid] + spart[1][tid] + spart[2][tid] + spart[3][tid]
                + spart[4][tid] + spart[5][tid] + spart[6][tid] + spart[7][tid];
        int r  = blockIdx.y * 16 + (tid >> 4);
        int cc = blockIdx.x * 16 + (tid & 15);
        if (r < HH && cc < WW)
            out[b * NPIX + r * WW + cc] = v;
    }
}

extern "C" void kernel_launch(void* const* d_in, const int* in_sizes, int n_in,
                              void* d_out, int out_size) {
    const float* stim   = (const float*)d_in[0];  // (8,225,3)
    const float* params = (const float*)d_in[1];  // (8,13)
    const float* ex     = (const float*)d_in[2];  // (1,225)
    const float* ey     = (const float*)d_in[3];  // (1,225)
    const float* slopes = (const float*)d_in[4];  // (200,200)
    // d_in[5] = pixelgrid: implied analytically, unused

    dim3 grid(TILES_X, TILES_Y, NB);   // (8,8,8) = 512 blocks x 256 threads
    mvg_kernel<<<grid, 256>>>(stim, params, ex, ey, slopes, (float*)d_out);
}